// round 6
// baseline (speedup 1.0000x reference)
#include <cuda_runtime.h>
#include <math_constants.h>

// DarkChannel fused, intra-thread software pipeline:
// Every thread both produces (channel-min + vertical 15-min van Herk -> smem)
// and consumes (horizontal 15-min from smem -> out). Per epoch e:
//   1) issue phase-1 loads for tile e           (45 independent LDG.64)
//   2) phase-2 for tile e-1 from other buffer   (runs under load shadow)
//   3) finish phase-1 min-chain + smem stores
//   4) __syncthreads
// Double-buffered eroded tile; K_TILES consecutive y-tiles per block.
//
// img [16,3,1024,1024] f32 -> out [16,1,1024,1024] f32, +inf border erosion.

#define IMG_H 1024
#define IMG_W 1024
#define IMG_B 16
#define CH_STRIDE (IMG_H * IMG_W)
#define YTILE 15
#define NUM_TY 69
#define XSPAN 256
#define HALO 8
#define SROW (XSPAN + 2 * HALO)        // 272
#define K_TILES 5
#define NTHREADS 160                   // 136 active in phase 1, all in phase 2

__device__ __forceinline__ float2 min2(float2 a, float2 b) {
    return make_float2(fminf(a.x, b.x), fminf(a.y, b.y));
}

template <bool CHECKY>
__device__ __forceinline__ float2 cmin2(const float* p, int y, bool vx) {
    if (!vx || (CHECKY && (unsigned)y >= (unsigned)IMG_H)) {
        return make_float2(CUDART_INF_F, CUDART_INF_F);
    }
    const float* r = p + (size_t)y * IMG_W;
    float2 c0 = *reinterpret_cast<const float2*>(r);
    float2 c1 = *reinterpret_cast<const float2*>(r + CH_STRIDE);
    float2 c2 = *reinterpret_cast<const float2*>(r + 2 * CH_STRIDE);
    return min2(min2(c0, c1), c2);
}

// Phase-2 horizontal 15-min for one finished tile in smem.
__device__ __forceinline__ void horiz(const float* B, float* outb,
                                      int y0, int X0, int tid) {
    const int vrows = min(YTILE, IMG_H - y0);
    const int nq = (XSPAN / 4) * vrows;            // 64 quads per row

    for (int i = tid; i < nq; i += NTHREADS) {
        const int r = i >> 6;
        const int c = i & 63;
        const float* row = &B[r * SROW];
        const int L0 = (c << 2) + HALO;

        float f[20];
#pragma unroll
        for (int q = 0; q < 5; ++q) {
            float4 v = *reinterpret_cast<const float4*>(&row[L0 - 8 + 4 * q]);
            f[q * 4 + 0] = v.x;
            f[q * 4 + 1] = v.y;
            f[q * 4 + 2] = v.z;
            f[q * 4 + 3] = v.w;
        }

        float core = f[4];
#pragma unroll
        for (int k = 5; k <= 15; ++k) core = fminf(core, f[k]);

        float p23   = fminf(f[2], f[3]);
        float p1617 = fminf(f[16], f[17]);

        float4 o;
        o.x = fminf(core, fminf(f[1], p23));
        o.y = fminf(core, fminf(p23, f[16]));
        o.z = fminf(core, fminf(f[3], p1617));
        o.w = fminf(core, fminf(p1617, f[18]));

        float* op = outb + (size_t)(y0 + r) * IMG_W + X0 + (c << 2);
        *reinterpret_cast<float4*>(op) = o;
    }
}

template <bool CHECKY>
__device__ __forceinline__ void epoch_body(const float* p, bool vx, bool do1,
                                           int y0, float* s,
                                           bool do2, const float* Bprev,
                                           float* outb, int y0prev, int X0, int tid) {
    float2 h[YTILE];
    // (1) issue the 15-row load batch (45 independent LDG.64)
    if (do1) {
#pragma unroll
        for (int t = 0; t < YTILE; ++t) {
            h[t] = cmin2<CHECKY>(p, y0 - 7 + t, vx);
        }
    }

    // (2) independent phase-2 work executes under the load shadow
    if (do2) {
        horiz(Bprev, outb, y0prev, X0, tid);
    }

    // (3) consume loads: suffix mins, then streaming prefix with 14 more rows
    if (do1) {
#pragma unroll
        for (int t = YTILE - 2; t >= 0; --t) {
            h[t] = min2(h[t], h[t + 1]);
        }
        *reinterpret_cast<float2*>(&s[0]) = h[0];

        float2 g = make_float2(CUDART_INF_F, CUDART_INF_F);
#pragma unroll
        for (int r = 1; r < YTILE; ++r) {
            g = min2(g, cmin2<CHECKY>(p, y0 + 7 + r, vx));
            *reinterpret_cast<float2*>(&s[r * SROW]) = min2(h[r], g);
        }
    }
}

extern "C" __global__ __launch_bounds__(NTHREADS, 6)
void k_fused(const float* __restrict__ img, float* __restrict__ out) {
    __shared__ float buf[2][YTILE * SROW];         // 2 x 16320 B

    const int tid = threadIdx.x;
    const int bx  = blockIdx.x;                    // x strip 0..3
    const int ty0 = blockIdx.y * K_TILES;
    const int b   = blockIdx.z;
    const int X0  = bx * XSPAN;

    const float* imgb = img + (size_t)b * 3 * CH_STRIDE;
    float* outb = out + (size_t)b * IMG_H * IMG_W;

    const int lc = tid << 1;
    const int gx = X0 - HALO + lc;
    const bool vx = (unsigned)gx < (unsigned)IMG_W;
    const float* p = imgb + gx;

#pragma unroll 1
    for (int e = 0; e <= K_TILES; ++e) {
        const int ty = ty0 + e;
        const bool do1 = (e < K_TILES) && (ty < NUM_TY) && (lc < SROW);
        const bool do2 = (e >= 1) && (ty0 + e - 1 < NUM_TY);
        const int y0 = ty * YTILE;
        const int y0prev = (ty - 1) * YTILE;
        float* s = &buf[e & 1][lc];
        const float* Bprev = buf[(e - 1) & 1];

        if (ty >= 1 && ty <= 66) {
            epoch_body<false>(p, vx, do1, y0, s, do2, Bprev, outb, y0prev, X0, tid);
        } else {
            epoch_body<true>(p, vx, do1, y0, s, do2, Bprev, outb, y0prev, X0, tid);
        }
        __syncthreads();
    }
}

extern "C" void kernel_launch(void* const* d_in, const int* in_sizes, int n_in,
                              void* d_out, int out_size) {
    const float* img = (const float*)d_in[0];
    float* out = (float*)d_out;

    dim3 grid(IMG_W / XSPAN, (NUM_TY + K_TILES - 1) / K_TILES, IMG_B);  // 4 x 14 x 16
    k_fused<<<grid, NTHREADS>>>(img, out);
}

// round 7
// speedup vs baseline: 1.6795x; 1.6795x over previous
#include <cuda_runtime.h>
#include <math_constants.h>

// DarkChannel fused (R4 structure, scalar columns for max occupancy):
//   phase 1: channel-min(C=3) + vertical 15-min van Herk, 1 float col/thread
//   phase 2: horizontal 15-min from smem tile (float4 LDS), write out
//
// img [16,3,1024,1024] f32 -> out [16,1,1024,1024] f32, +inf border erosion.

#define IMG_H 1024
#define IMG_W 1024
#define IMG_B 16
#define CH_STRIDE (IMG_H * IMG_W)
#define YTILE 15
#define NUM_TY 69
#define XSPAN 512
#define HALO 8
#define SROW (XSPAN + 2 * HALO)        // 528
#define NTHREADS 544                   // 528 active in phase 1

__device__ __forceinline__ float cmin1_raw(const float* r) {
    float c0 = __ldg(r);
    float c1 = __ldg(r + CH_STRIDE);
    float c2 = __ldg(r + 2 * CH_STRIDE);
    return fminf(fminf(c0, c1), c2);
}

template <bool CHECKY>
__device__ __forceinline__ float cmin1(const float* p, int y, bool vx) {
    if (!vx || (CHECKY && (unsigned)y >= (unsigned)IMG_H)) {
        return CUDART_INF_F;
    }
    return cmin1_raw(p + (size_t)y * IMG_W);
}

// Vertical van Herk (block == window == 15) for one scalar column.
template <bool CHECKY>
__device__ __forceinline__ void vert(const float* p, bool vx, int y0, float* s) {
    float h[YTILE];
#pragma unroll
    for (int t = 0; t < YTILE; ++t) {
        h[t] = cmin1<CHECKY>(p, y0 - 7 + t, vx);       // rows y0-7 .. y0+7
    }
#pragma unroll
    for (int t = YTILE - 2; t >= 0; --t) {
        h[t] = fminf(h[t], h[t + 1]);                  // suffix mins
    }

    s[0] = h[0];

    float g = CUDART_INF_F;
#pragma unroll
    for (int r = 1; r < YTILE; ++r) {
        g = fminf(g, cmin1<CHECKY>(p, y0 + 7 + r, vx)); // next-block prefix
        s[r * SROW] = fminf(h[r], g);
    }
}

extern "C" __global__ __launch_bounds__(NTHREADS, 3)
void k_fused(const float* __restrict__ img, float* __restrict__ out) {
    __shared__ float sV[YTILE * SROW];                 // 31680 B

    const int tid = threadIdx.x;
    const int bx  = blockIdx.x;                        // x strip 0..1
    const int ty  = blockIdx.y;                        // y tile 0..68
    const int b   = blockIdx.z;
    const int y0  = ty * YTILE;
    const int X0  = bx * XSPAN;

    // ---- Phase 1: vertical erosion of SROW columns (incl. +/-8 halo) ----
    if (tid < SROW) {
        const int gx = X0 - HALO + tid;
        const bool vx = (unsigned)gx < (unsigned)IMG_W;
        const float* p = img + (size_t)b * 3 * CH_STRIDE + gx;
        if (ty >= 1 && ty <= 66) {
            vert<false>(p, vx, y0, &sV[tid]);
        } else {
            vert<true>(p, vx, y0, &sV[tid]);
        }
    }

    __syncthreads();

    // ---- Phase 2: horizontal 15-min from smem ----
    const int vrows = min(YTILE, IMG_H - y0);
    const int nq = (XSPAN / 4) * vrows;                // 128 quads per row
    float* outb = out + (size_t)b * IMG_H * IMG_W;

    for (int i = tid; i < nq; i += NTHREADS) {
        const int r = i >> 7;
        const int c = i & 127;
        const float* row = &sV[r * SROW];
        const int L0 = (c << 2) + HALO;                // local col of output 0

        float f[20];
#pragma unroll
        for (int q = 0; q < 5; ++q) {
            float4 v = *reinterpret_cast<const float4*>(&row[L0 - 8 + 4 * q]);
            f[q * 4 + 0] = v.x;
            f[q * 4 + 1] = v.y;
            f[q * 4 + 2] = v.z;
            f[q * 4 + 3] = v.w;
        }

        float core = f[4];
#pragma unroll
        for (int k = 5; k <= 15; ++k) core = fminf(core, f[k]);

        float p23   = fminf(f[2], f[3]);
        float p1617 = fminf(f[16], f[17]);

        float4 o;
        o.x = fminf(core, fminf(f[1], p23));
        o.y = fminf(core, fminf(p23, f[16]));
        o.z = fminf(core, fminf(f[3], p1617));
        o.w = fminf(core, fminf(p1617, f[18]));

        float* op = outb + (size_t)(y0 + r) * IMG_W + X0 + (c << 2);
        *reinterpret_cast<float4*>(op) = o;
    }
}

extern "C" void kernel_launch(void* const* d_in, const int* in_sizes, int n_in,
                              void* d_out, int out_size) {
    const float* img = (const float*)d_in[0];
    float* out = (float*)d_out;

    dim3 grid(IMG_W / XSPAN, NUM_TY, IMG_B);           // 2 x 69 x 16
    k_fused<<<grid, NTHREADS>>>(img, out);
}

// round 8
// speedup vs baseline: 1.7878x; 1.0645x over previous
#include <cuda_runtime.h>
#include <math_constants.h>

// DarkChannel fused, 30-row tiles via chained van Herk:
//   phase 1: channel-min(C=3) + vertical 15-min over 30 output rows using two
//            chained van Herk blocks (streamed rows of block 1 captured in regs
//            as block 2's suffix array): 44 input rows / 30 output rows.
//   phase 2: horizontal 15-min from smem tile (float4 LDS), streaming stores.
//
// img [16,3,1024,1024] f32 -> out [16,1,1024,1024] f32, +inf border erosion.

#define IMG_H 1024
#define IMG_W 1024
#define IMG_B 16
#define CH_STRIDE (IMG_H * IMG_W)
#define YTILE 30
#define NUM_TY 35                      // ceil(1024/30)
#define XSPAN 512
#define HALO 8
#define SROW (XSPAN + 2 * HALO)        // 528
#define NTHREADS 288                   // 264 active in phase 1

__device__ __forceinline__ float2 min2(float2 a, float2 b) {
    return make_float2(fminf(a.x, b.x), fminf(a.y, b.y));
}

template <bool CHECKY>
__device__ __forceinline__ float2 cmin2(const float* p, int y, bool vx) {
    if (!vx || (CHECKY && (unsigned)y >= (unsigned)IMG_H)) {
        return make_float2(CUDART_INF_F, CUDART_INF_F);
    }
    const float* r = p + (size_t)y * IMG_W;
    float2 c0 = *reinterpret_cast<const float2*>(r);
    float2 c1 = *reinterpret_cast<const float2*>(r + CH_STRIDE);
    float2 c2 = *reinterpret_cast<const float2*>(r + 2 * CH_STRIDE);
    return min2(min2(c0, c1), c2);
}

// Two chained van Herk blocks (window 15, block 15) producing 30 eroded rows
// into smem at stride SROW, reading 44 input rows.
template <bool CHECKY>
__device__ __forceinline__ void vert30(const float* p, bool vx, int y0, float* s) {
    const float2 INF2 = make_float2(CUDART_INF_F, CUDART_INF_F);

    // ---- block 1: out rows y0..y0+14 ----
    float2 h[15];
#pragma unroll
    for (int t = 0; t < 15; ++t) {
        h[t] = cmin2<CHECKY>(p, y0 - 7 + t, vx);       // rows y0-7 .. y0+7
    }
#pragma unroll
    for (int t = 13; t >= 0; --t) {
        h[t] = min2(h[t], h[t + 1]);                   // suffix mins
    }
    *reinterpret_cast<float2*>(&s[0]) = h[0];

    float2 n[15];                                      // rows y0+8 .. y0+22 (raw)
    float2 g = INF2;
#pragma unroll
    for (int k = 1; k < 15; ++k) {
        float2 v = cmin2<CHECKY>(p, y0 + 7 + k, vx);   // row y0+7+k
        n[k - 1] = v;                                  // captured for block 2
        g = min2(g, v);
        *reinterpret_cast<float2*>(&s[k * SROW]) = min2(h[k], g);
    }
    n[14] = cmin2<CHECKY>(p, y0 + 22, vx);

    // ---- block 2: out rows y0+15..y0+29 ----
#pragma unroll
    for (int t = 13; t >= 0; --t) {
        n[t] = min2(n[t], n[t + 1]);                   // suffix mins
    }
    *reinterpret_cast<float2*>(&s[15 * SROW]) = n[0];

    g = INF2;
#pragma unroll
    for (int k = 1; k < 15; ++k) {
        float2 v = cmin2<CHECKY>(p, y0 + 22 + k, vx);  // rows y0+23 .. y0+36
        g = min2(g, v);
        *reinterpret_cast<float2*>(&s[(15 + k) * SROW]) = min2(n[k], g);
    }
}

extern "C" __global__ __launch_bounds__(NTHREADS, 3)
void k_fused(const float* __restrict__ img, float* __restrict__ out) {
    extern __shared__ float sV[];                      // YTILE * SROW (63360 B)

    const int tid = threadIdx.x;
    const int bx  = blockIdx.x;                        // x strip 0..1
    const int ty  = blockIdx.y;                        // y tile 0..34
    const int b   = blockIdx.z;
    const int y0  = ty * YTILE;
    const int X0  = bx * XSPAN;

    // ---- Phase 1: vertical erosion of SROW cols (incl. +/-8 halo) ----
    if (tid < SROW / 2) {                              // 264 active threads
        const int lc = tid << 1;
        const int gx = X0 - HALO + lc;
        const bool vx = (unsigned)gx < (unsigned)IMG_W;
        const float* p = img + (size_t)b * 3 * CH_STRIDE + gx;
        if (ty >= 1 && ty <= 32) {
            vert30<false>(p, vx, y0, &sV[lc]);         // rows y0-7..y0+36 in range
        } else {
            vert30<true>(p, vx, y0, &sV[lc]);
        }
    }

    __syncthreads();

    // ---- Phase 2: horizontal 15-min from smem ----
    const int vrows = min(YTILE, IMG_H - y0);          // last tile: 4
    const int nq = (XSPAN / 4) * vrows;                // 128 quads per row
    float* outb = out + (size_t)b * IMG_H * IMG_W;

    for (int i = tid; i < nq; i += NTHREADS) {
        const int r = i >> 7;
        const int c = i & 127;
        const float* row = &sV[r * SROW];
        const int L0 = (c << 2) + HALO;

        float f[20];
#pragma unroll
        for (int q = 0; q < 5; ++q) {
            float4 v = *reinterpret_cast<const float4*>(&row[L0 - 8 + 4 * q]);
            f[q * 4 + 0] = v.x;
            f[q * 4 + 1] = v.y;
            f[q * 4 + 2] = v.z;
            f[q * 4 + 3] = v.w;
        }

        float core = f[4];
#pragma unroll
        for (int k = 5; k <= 15; ++k) core = fminf(core, f[k]);

        float p23   = fminf(f[2], f[3]);
        float p1617 = fminf(f[16], f[17]);

        float4 o;
        o.x = fminf(core, fminf(f[1], p23));
        o.y = fminf(core, fminf(p23, f[16]));
        o.z = fminf(core, fminf(f[3], p1617));
        o.w = fminf(core, fminf(p1617, f[18]));

        float* op = outb + (size_t)(y0 + r) * IMG_W + X0 + (c << 2);
        __stcs(reinterpret_cast<float4*>(op), o);      // streaming store
    }
}

extern "C" void kernel_launch(void* const* d_in, const int* in_sizes, int n_in,
                              void* d_out, int out_size) {
    const float* img = (const float*)d_in[0];
    float* out = (float*)d_out;

    const int smem = YTILE * SROW * sizeof(float);     // 63360 B > 48K -> opt-in
    static bool attr_set = false;
    if (!attr_set) {
        cudaFuncSetAttribute(k_fused, cudaFuncAttributeMaxDynamicSharedMemorySize, smem);
        attr_set = true;
    }

    dim3 grid(IMG_W / XSPAN, NUM_TY, IMG_B);           // 2 x 35 x 16 = 1120
    k_fused<<<grid, NTHREADS, smem>>>(img, out);
}